// round 1
// baseline (speedup 1.0000x reference)
#include <cuda_runtime.h>
#include <cuda_bf16.h>
#include <mma.h>

using namespace nvcuda;

#define N_TOK 4096
#define D_MODEL 512
#define NH 8
#define DH 64
#define LDS 72   // padded leading dim for 64-wide smem tiles (multiple of 4 floats)

// ---- device scratch (no cudaMalloc allowed) ----
__device__ float g_Q[(size_t)N_TOK * D_MODEL];
__device__ float g_K[(size_t)N_TOK * D_MODEL];
__device__ float g_V[(size_t)N_TOK * D_MODEL];
__device__ float g_AO[(size_t)N_TOK * D_MODEL];
__device__ float g_dist[(size_t)N_TOK * N_TOK];

// ============================================================
// Pairwise Euclidean distance: dist[i][j] = ||coords[i]-coords[j]||
// ============================================================
__global__ void dist_kernel(const float* __restrict__ coords, float* __restrict__ dist) {
    size_t t = (size_t)blockIdx.x * blockDim.x + threadIdx.x;
    const size_t total = (size_t)N_TOK * N_TOK / 4;
    if (t >= total) return;
    int i  = (int)(t >> 10);           // 1024 float4 groups per row
    int j0 = ((int)t & 1023) << 2;
    float cx = coords[2 * i], cy = coords[2 * i + 1];
    float4 out;
#pragma unroll
    for (int u = 0; u < 4; u++) {
        int j = j0 + u;
        float dx = cx - coords[2 * j];
        float dy = cy - coords[2 * j + 1];
        float d2 = dx * dx + dy * dy;
        ((float*)&out)[u] = (d2 > 0.f) ? d2 * rsqrtf(d2) : 0.f;
    }
    *(float4*)(dist + ((size_t)i << 12) + j0) = out;
}

// ============================================================
// C[M,N] = A[M,K] @ W[N,K]^T + bias[N]   (tf32 wmma, 64x64 CTA tile)
// M=4096, N=512, K=512 fixed. grid = (M/64, N/64), 128 threads.
// ============================================================
__global__ __launch_bounds__(128) void gemm64(
    const float* __restrict__ A, const float* __restrict__ W,
    const float* __restrict__ bias, float* __restrict__ C) {
    __shared__ float sA[64 * LDS];
    __shared__ float sW[64 * LDS];
    __shared__ float stage[4][16 * 20];

    int m0 = blockIdx.x * 64, n0 = blockIdx.y * 64;
    int tid = threadIdx.x, warp = tid >> 5, lane = tid & 31;

    wmma::fragment<wmma::accumulator, 16, 16, 8, float> c[4];
#pragma unroll
    for (int nt = 0; nt < 4; nt++) wmma::fill_fragment(c[nt], 0.f);

    for (int kt = 0; kt < D_MODEL; kt += 64) {
        for (int i = tid; i < 64 * 16; i += 128) {
            int r = i >> 4, c4 = (i & 15) << 2;
            *(float4*)&sA[r * LDS + c4] =
                *(const float4*)&A[(size_t)(m0 + r) * D_MODEL + kt + c4];
            *(float4*)&sW[r * LDS + c4] =
                *(const float4*)&W[(size_t)(n0 + r) * D_MODEL + kt + c4];
        }
        __syncthreads();
#pragma unroll
        for (int ks = 0; ks < 64; ks += 8) {
            wmma::fragment<wmma::matrix_a, 16, 16, 8, wmma::precision::tf32, wmma::row_major> a;
            wmma::load_matrix_sync(a, &sA[warp * 16 * LDS + ks], LDS);
#pragma unroll
            for (int i = 0; i < a.num_elements; i++) a.x[i] = wmma::__float_to_tf32(a.x[i]);
#pragma unroll
            for (int nt = 0; nt < 4; nt++) {
                wmma::fragment<wmma::matrix_b, 16, 16, 8, wmma::precision::tf32, wmma::col_major> b;
                wmma::load_matrix_sync(b, &sW[nt * 16 * LDS + ks], LDS);
#pragma unroll
                for (int i = 0; i < b.num_elements; i++) b.x[i] = wmma::__float_to_tf32(b.x[i]);
                wmma::mma_sync(c[nt], a, b, c[nt]);
            }
        }
        __syncthreads();
    }
    // epilogue: stage per warp, add bias, store
#pragma unroll
    for (int nt = 0; nt < 4; nt++) {
        wmma::store_matrix_sync(&stage[warp][0], c[nt], 20, wmma::mem_row_major);
        __syncwarp();
        for (int e = lane; e < 256; e += 32) {
            int r = e >> 4, cc = e & 15;
            C[(size_t)(m0 + warp * 16 + r) * D_MODEL + n0 + nt * 16 + cc] =
                stage[warp][r * 20 + cc] + bias[n0 + nt * 16 + cc];
        }
        __syncwarp();
    }
}

// ============================================================
// Flash attention, one (head, 64-row q tile) per CTA, online softmax,
// tf32 wmma for S = Q@K^T and O += P@V. 128 threads.
// ============================================================
__global__ __launch_bounds__(128) void flash64(
    const float* __restrict__ Qg, const float* __restrict__ Kg,
    const float* __restrict__ Vg, const float* __restrict__ dist,
    float* __restrict__ Og) {
    extern __shared__ float sm[];
    float* sQ = sm;
    float* sK = sQ + 64 * LDS;
    float* sV = sK + 64 * LDS;
    float* sS = sV + 64 * LDS;
    float* sO = sS + 64 * LDS;
    float* m_prev = sO + 64 * LDS;   // 64
    float* l_sum  = m_prev + 64;     // 64
    float* alpha  = l_sum + 64;      // 64
    float* red    = alpha + 64;      // 128
    float* red2   = red + 128;       // 128

    int tid = threadIdx.x, warp = tid >> 5;
    int q0 = blockIdx.x * 64;
    int h  = blockIdx.y;
    const float slope = exp2f(-(float)(h + 1));   // get_slopes(8) = 2^-(h+1)
    const float scale = 0.125f;                   // 1/sqrt(64)

    // load scaled Q tile
    for (int i = tid; i < 64 * 16; i += 128) {
        int r = i >> 4, c4 = (i & 15) << 2;
        float4 v = *(const float4*)&Qg[(size_t)(q0 + r) * D_MODEL + h * DH + c4];
        v.x *= scale; v.y *= scale; v.z *= scale; v.w *= scale;
        *(float4*)&sQ[r * LDS + c4] = v;
    }
    for (int i = tid; i < 64 * LDS; i += 128) sO[i] = 0.f;
    if (tid < 64) { m_prev[tid] = -1e30f; l_sum[tid] = 0.f; }
    __syncthreads();

    for (int k0 = 0; k0 < N_TOK; k0 += 64) {
        // load K,V tiles
        for (int i = tid; i < 64 * 16; i += 128) {
            int r = i >> 4, c4 = (i & 15) << 2;
            *(float4*)&sK[r * LDS + c4] =
                *(const float4*)&Kg[(size_t)(k0 + r) * D_MODEL + h * DH + c4];
            *(float4*)&sV[r * LDS + c4] =
                *(const float4*)&Vg[(size_t)(k0 + r) * D_MODEL + h * DH + c4];
        }
        __syncthreads();

        // S = (Q*scale) @ K^T
#pragma unroll
        for (int nt = 0; nt < 4; nt++) {
            wmma::fragment<wmma::accumulator, 16, 16, 8, float> cfr;
            wmma::fill_fragment(cfr, 0.f);
#pragma unroll
            for (int ks = 0; ks < 64; ks += 8) {
                wmma::fragment<wmma::matrix_a, 16, 16, 8, wmma::precision::tf32, wmma::row_major> a;
                wmma::load_matrix_sync(a, &sQ[warp * 16 * LDS + ks], LDS);
#pragma unroll
                for (int i = 0; i < a.num_elements; i++) a.x[i] = wmma::__float_to_tf32(a.x[i]);
                wmma::fragment<wmma::matrix_b, 16, 16, 8, wmma::precision::tf32, wmma::col_major> b;
                wmma::load_matrix_sync(b, &sK[nt * 16 * LDS + ks], LDS);
#pragma unroll
                for (int i = 0; i < b.num_elements; i++) b.x[i] = wmma::__float_to_tf32(b.x[i]);
                wmma::mma_sync(cfr, a, b, cfr);
            }
            wmma::store_matrix_sync(&sS[warp * 16 * LDS + nt * 16], cfr, LDS, wmma::mem_row_major);
        }
        __syncthreads();

        // bias: S -= slope * dist
        for (int i = tid; i < 4096; i += 128) {
            int r = i >> 6, cc = i & 63;
            sS[r * LDS + cc] -= slope * dist[(size_t)(q0 + r) * N_TOK + k0 + cc];
        }
        __syncthreads();

        // online softmax (two threads per row, 32 cols each)
        {
            int r = tid & 63, hf = tid >> 6, c0 = hf * 32;
            float mloc = -1e30f;
#pragma unroll 8
            for (int cc = 0; cc < 32; cc++) mloc = fmaxf(mloc, sS[r * LDS + c0 + cc]);
            red[hf * 64 + r] = mloc;
            __syncthreads();
            float m_new = fmaxf(m_prev[r], fmaxf(red[r], red[64 + r]));
            float sloc = 0.f;
#pragma unroll 8
            for (int cc = 0; cc < 32; cc++) {
                float p = __expf(sS[r * LDS + c0 + cc] - m_new);
                sS[r * LDS + c0 + cc] = p;
                sloc += p;
            }
            red2[hf * 64 + r] = sloc;
            __syncthreads();
            if (hf == 0) {
                float al = __expf(m_prev[r] - m_new);
                l_sum[r] = l_sum[r] * al + red2[r] + red2[64 + r];
                m_prev[r] = m_new;
                alpha[r] = al;
            }
            __syncthreads();
        }

        // rescale O
        for (int i = tid; i < 4096; i += 128) {
            int rr = i >> 6, cc = i & 63;
            sO[rr * LDS + cc] *= alpha[rr];
        }
        __syncthreads();

        // O += P @ V
#pragma unroll
        for (int nt = 0; nt < 4; nt++) {
            wmma::fragment<wmma::accumulator, 16, 16, 8, float> cfr;
            wmma::load_matrix_sync(cfr, &sO[warp * 16 * LDS + nt * 16], LDS, wmma::mem_row_major);
#pragma unroll
            for (int ks = 0; ks < 8; ks++) {
                wmma::fragment<wmma::matrix_a, 16, 16, 8, wmma::precision::tf32, wmma::row_major> a;
                wmma::load_matrix_sync(a, &sS[warp * 16 * LDS + ks * 8], LDS);
#pragma unroll
                for (int i = 0; i < a.num_elements; i++) a.x[i] = wmma::__float_to_tf32(a.x[i]);
                wmma::fragment<wmma::matrix_b, 16, 16, 8, wmma::precision::tf32, wmma::row_major> b;
                wmma::load_matrix_sync(b, &sV[ks * 8 * LDS + nt * 16], LDS);
#pragma unroll
                for (int i = 0; i < b.num_elements; i++) b.x[i] = wmma::__float_to_tf32(b.x[i]);
                wmma::mma_sync(cfr, a, b, cfr);
            }
            wmma::store_matrix_sync(&sO[warp * 16 * LDS + nt * 16], cfr, LDS, wmma::mem_row_major);
        }
        __syncthreads();
    }

    // final normalize + store (layout [n, 512] so out-proj GEMM consumes directly)
    for (int i = tid; i < 4096; i += 128) {
        int r = i >> 6, cc = i & 63;
        Og[(size_t)(q0 + r) * D_MODEL + h * DH + cc] = sO[r * LDS + cc] / l_sum[r];
    }
}

// ============================================================
// launcher
// ============================================================
extern "C" void kernel_launch(void* const* d_in, const int* in_sizes, int n_in,
                              void* d_out, int out_size) {
    const float* x      = (const float*)d_in[0];
    const float* coords = (const float*)d_in[1];
    const float* Wq = (const float*)d_in[2]; const float* bq = (const float*)d_in[3];
    const float* Wk = (const float*)d_in[4]; const float* bk = (const float*)d_in[5];
    const float* Wv = (const float*)d_in[6]; const float* bv = (const float*)d_in[7];
    const float* Wo = (const float*)d_in[8]; const float* bo = (const float*)d_in[9];
    float* out = (float*)d_out;

    float *pQ, *pK, *pV, *pAO, *pD;
    cudaGetSymbolAddress((void**)&pQ, g_Q);
    cudaGetSymbolAddress((void**)&pK, g_K);
    cudaGetSymbolAddress((void**)&pV, g_V);
    cudaGetSymbolAddress((void**)&pAO, g_AO);
    cudaGetSymbolAddress((void**)&pD, g_dist);

    const size_t FLASH_SMEM = (5 * 64 * LDS + 3 * 64 + 256) * sizeof(float);
    cudaFuncSetAttribute(flash64, cudaFuncAttributeMaxDynamicSharedMemorySize, (int)FLASH_SMEM);

    // pairwise distances (once)
    {
        size_t total = (size_t)N_TOK * N_TOK / 4;
        dist_kernel<<<(unsigned)((total + 255) / 256), 256>>>(coords, pD);
    }

    dim3 gg(N_TOK / 64, D_MODEL / 64);   // (64, 8)
    gemm64<<<gg, 128>>>(x, Wq, bq, pQ);
    gemm64<<<gg, 128>>>(x, Wk, bk, pK);
    gemm64<<<gg, 128>>>(x, Wv, bv, pV);

    flash64<<<dim3(N_TOK / 64, NH), 128, FLASH_SMEM>>>(pQ, pK, pV, pD, pAO);

    gemm64<<<gg, 128>>>(pAO, Wo, bo, out);
}

// round 2
// speedup vs baseline: 2.6240x; 2.6240x over previous
#include <cuda_runtime.h>
#include <cuda_bf16.h>
#include <mma.h>

using namespace nvcuda;

#define N_TOK 4096
#define D_MODEL 512
#define NH 8
#define DH 64
#define LDS 72      // gemm64 smem pitch
#define PITCH 72    // flash smem row pitch (floats)

// ---- device scratch (no cudaMalloc allowed) ----
__device__ float g_Q[(size_t)N_TOK * D_MODEL];
__device__ float g_K[(size_t)N_TOK * D_MODEL];
__device__ float g_V[(size_t)N_TOK * D_MODEL];
__device__ float g_AO[(size_t)N_TOK * D_MODEL];

// ============================================================
// helpers
// ============================================================
__device__ __forceinline__ unsigned tf32u(float x) {
    unsigned u;
    asm("cvt.rna.tf32.f32 %0, %1;" : "=r"(u) : "f"(x));
    return u;
}
__device__ __forceinline__ float tf32f(float x) {
    return __uint_as_float(tf32u(x));
}

// D += A(16x8) @ B(8x8), tf32, m16n8k8 row.col
__device__ __forceinline__ void mma_tf32(float d[4],
    unsigned a0, unsigned a1, unsigned a2, unsigned a3,
    unsigned b0, unsigned b1) {
    asm volatile(
        "mma.sync.aligned.m16n8k8.row.col.f32.tf32.tf32.f32 "
        "{%0,%1,%2,%3},{%4,%5,%6,%7},{%8,%9},{%0,%1,%2,%3};\n"
        : "+f"(d[0]), "+f"(d[1]), "+f"(d[2]), "+f"(d[3])
        : "r"(a0), "r"(a1), "r"(a2), "r"(a3), "r"(b0), "r"(b1));
}

__device__ __forceinline__ float edist(float qx, float qy, float2 k) {
    float dx = qx - k.x, dy = qy - k.y;
    float d2 = dx * dx + dy * dy;
    return d2 > 0.f ? d2 * rsqrtf(d2) : 0.f;
}

// permuted column index: blocks of 16 (by d mod 4) at stride 18 -> b-frag pairs
// (cols d, d+4 of a k-chunk) land at adjacent, 8B-aligned floats, conflict-free.
__device__ __forceinline__ int pidx(int d) { return (d & 3) * 18 + (d >> 2); }

// ============================================================
// GEMM: C[M,N] = A[M,K] @ W[N,K]^T + bias[N]  (tf32 wmma, 64x64 tile)
// blockIdx.z selects one of up to 3 (W, bias, C) triples.
// ============================================================
struct GemmArgs { const float* W; const float* bias; float* C; };
struct GemmArgs3 { GemmArgs a[3]; };

__global__ __launch_bounds__(128) void gemm64(
    const float* __restrict__ A, GemmArgs3 args) {
    const float* __restrict__ W    = args.a[blockIdx.z].W;
    const float* __restrict__ bias = args.a[blockIdx.z].bias;
    float* __restrict__ C          = args.a[blockIdx.z].C;

    __shared__ float sA[64 * LDS];
    __shared__ float sW[64 * LDS];
    __shared__ float stage[4][16 * 20];

    int m0 = blockIdx.x * 64, n0 = blockIdx.y * 64;
    int tid = threadIdx.x, warp = tid >> 5, lane = tid & 31;

    wmma::fragment<wmma::accumulator, 16, 16, 8, float> c[4];
#pragma unroll
    for (int nt = 0; nt < 4; nt++) wmma::fill_fragment(c[nt], 0.f);

    for (int kt = 0; kt < D_MODEL; kt += 64) {
        for (int i = tid; i < 64 * 16; i += 128) {
            int r = i >> 4, c4 = (i & 15) << 2;
            *(float4*)&sA[r * LDS + c4] =
                *(const float4*)&A[(size_t)(m0 + r) * D_MODEL + kt + c4];
            *(float4*)&sW[r * LDS + c4] =
                *(const float4*)&W[(size_t)(n0 + r) * D_MODEL + kt + c4];
        }
        __syncthreads();
#pragma unroll
        for (int ks = 0; ks < 64; ks += 8) {
            wmma::fragment<wmma::matrix_a, 16, 16, 8, wmma::precision::tf32, wmma::row_major> a;
            wmma::load_matrix_sync(a, &sA[warp * 16 * LDS + ks], LDS);
#pragma unroll
            for (int i = 0; i < a.num_elements; i++) a.x[i] = wmma::__float_to_tf32(a.x[i]);
#pragma unroll
            for (int nt = 0; nt < 4; nt++) {
                wmma::fragment<wmma::matrix_b, 16, 16, 8, wmma::precision::tf32, wmma::col_major> b;
                wmma::load_matrix_sync(b, &sW[nt * 16 * LDS + ks], LDS);
#pragma unroll
                for (int i = 0; i < b.num_elements; i++) b.x[i] = wmma::__float_to_tf32(b.x[i]);
                wmma::mma_sync(c[nt], a, b, c[nt]);
            }
        }
        __syncthreads();
    }
#pragma unroll
    for (int nt = 0; nt < 4; nt++) {
        wmma::store_matrix_sync(&stage[warp][0], c[nt], 20, wmma::mem_row_major);
        __syncwarp();
        for (int e = lane; e < 256; e += 32) {
            int r = e >> 4, cc = e & 15;
            C[(size_t)(m0 + warp * 16 + r) * D_MODEL + n0 + nt * 16 + cc] =
                stage[warp][r * 20 + cc] + bias[n0 + nt * 16 + cc];
        }
        __syncwarp();
    }
}

// ============================================================
// Flash attention v2: register-resident S and O, raw mma.m16n8k8 tf32,
// on-the-fly distance bias, shuffle-based P re-layout.
// CTA: 256 thr (8 warps), q-tile 128 rows (16/warp), k-tile 64.
// ============================================================
__global__ __launch_bounds__(256, 2) void flash2(
    const float* __restrict__ Qg, const float* __restrict__ Kg,
    const float* __restrict__ Vg, const float* __restrict__ coords,
    float* __restrict__ Og) {
    extern __shared__ float sm[];
    float* sQ  = sm;                     // [128][PITCH] permuted dh
    float* sK  = sQ + 128 * PITCH;       // [64 tok][PITCH] permuted dh
    float* sVT = sK + 64 * PITCH;        // [64 dh][PITCH] permuted tok
    float* sKC = sVT + 64 * PITCH;       // [64] float2 coords

    const int tid = threadIdx.x;
    const int warp = tid >> 5, lane = tid & 31;
    const int g = lane >> 2, t = lane & 3;
    const int q0 = blockIdx.x * 128;
    const int h  = blockIdx.y;
    const float slope = exp2f(-(float)(h + 1));

    // ---- load Q tile: scaled by 1/8, tf32, permuted ----
    for (int i = tid; i < 128 * 16; i += 256) {
        int r = i >> 4, c4 = (i & 15) << 2;
        float4 v = *(const float4*)&Qg[(size_t)(q0 + r) * D_MODEL + h * DH + c4];
        float* row = &sQ[r * PITCH];
        int b = c4 >> 2;
        row[b]      = tf32f(v.x * 0.125f);
        row[b + 18] = tf32f(v.y * 0.125f);
        row[b + 36] = tf32f(v.z * 0.125f);
        row[b + 54] = tf32f(v.w * 0.125f);
    }
    // per-thread q coords (rows warp*16+g and +8)
    const int qr0 = q0 + warp * 16 + g;
    const float qx0 = coords[2 * qr0],       qy0 = coords[2 * qr0 + 1];
    const float qx1 = coords[2 * (qr0 + 8)], qy1 = coords[2 * (qr0 + 8) + 1];

    float o[8][4];
#pragma unroll
    for (int nt = 0; nt < 8; nt++) { o[nt][0] = o[nt][1] = o[nt][2] = o[nt][3] = 0.f; }
    float m0 = -1e30f, m1 = -1e30f, l0 = 0.f, l1 = 0.f;

    __syncthreads();

    for (int k0 = 0; k0 < N_TOK; k0 += 64) {
        // ---- load K tile (permuted dh) ----
        for (int i = tid; i < 64 * 16; i += 256) {
            int r = i >> 4, c4 = (i & 15) << 2;
            float4 v = *(const float4*)&Kg[(size_t)(k0 + r) * D_MODEL + h * DH + c4];
            float* row = &sK[r * PITCH];
            int b = c4 >> 2;
            row[b] = tf32f(v.x); row[b + 18] = tf32f(v.y);
            row[b + 36] = tf32f(v.z); row[b + 54] = tf32f(v.w);
        }
        // ---- load V tile transposed (sVT[dh][perm tok]) ----
        for (int i = tid; i < 64 * 16; i += 256) {
            int r = i >> 4, c4 = (i & 15) << 2;   // r = token, c4 = dh group
            float4 v = *(const float4*)&Vg[(size_t)(k0 + r) * D_MODEL + h * DH + c4];
            int pt = pidx(r);
            sVT[(c4 + 0) * PITCH + pt] = tf32f(v.x);
            sVT[(c4 + 1) * PITCH + pt] = tf32f(v.y);
            sVT[(c4 + 2) * PITCH + pt] = tf32f(v.z);
            sVT[(c4 + 3) * PITCH + pt] = tf32f(v.w);
        }
        if (tid < 64) ((float2*)sKC)[tid] = ((const float2*)coords)[k0 + tid];
        __syncthreads();

        // ---- S = Q @ K^T ----
        float s[8][4];
#pragma unroll
        for (int nt = 0; nt < 8; nt++) { s[nt][0] = s[nt][1] = s[nt][2] = s[nt][3] = 0.f; }
#pragma unroll
        for (int kc = 0; kc < 8; kc++) {
            uint2 aA = *(uint2*)&sQ[(warp * 16 + g) * PITCH + 18 * t + 2 * kc];     // a0,a2
            uint2 aB = *(uint2*)&sQ[(warp * 16 + g + 8) * PITCH + 18 * t + 2 * kc]; // a1,a3
#pragma unroll
            for (int nt = 0; nt < 8; nt++) {
                uint2 b = *(uint2*)&sK[(nt * 8 + g) * PITCH + 18 * t + 2 * kc];
                mma_tf32(s[nt], aA.x, aB.x, aA.y, aB.y, b.x, b.y);
            }
        }

        // ---- bias (on-the-fly distance) + row max ----
        float mt0 = -1e30f, mt1 = -1e30f;
#pragma unroll
        for (int nt = 0; nt < 8; nt++) {
            float2 ka = ((float2*)sKC)[nt * 8 + 2 * t];
            float2 kb = ((float2*)sKC)[nt * 8 + 2 * t + 1];
            s[nt][0] -= slope * edist(qx0, qy0, ka);
            s[nt][1] -= slope * edist(qx0, qy0, kb);
            s[nt][2] -= slope * edist(qx1, qy1, ka);
            s[nt][3] -= slope * edist(qx1, qy1, kb);
            mt0 = fmaxf(mt0, fmaxf(s[nt][0], s[nt][1]));
            mt1 = fmaxf(mt1, fmaxf(s[nt][2], s[nt][3]));
        }
        mt0 = fmaxf(mt0, __shfl_xor_sync(0xffffffffu, mt0, 1));
        mt0 = fmaxf(mt0, __shfl_xor_sync(0xffffffffu, mt0, 2));
        mt1 = fmaxf(mt1, __shfl_xor_sync(0xffffffffu, mt1, 1));
        mt1 = fmaxf(mt1, __shfl_xor_sync(0xffffffffu, mt1, 2));

        float mn0 = fmaxf(m0, mt0), mn1 = fmaxf(m1, mt1);
        float al0 = __expf(m0 - mn0), al1 = __expf(m1 - mn1);
        m0 = mn0; m1 = mn1;

        // ---- P = exp(S - m), row sums ----
        float ls0 = 0.f, ls1 = 0.f;
#pragma unroll
        for (int nt = 0; nt < 8; nt++) {
            s[nt][0] = __expf(s[nt][0] - mn0);
            s[nt][1] = __expf(s[nt][1] - mn0);
            s[nt][2] = __expf(s[nt][2] - mn1);
            s[nt][3] = __expf(s[nt][3] - mn1);
            ls0 += s[nt][0] + s[nt][1];
            ls1 += s[nt][2] + s[nt][3];
        }
        ls0 += __shfl_xor_sync(0xffffffffu, ls0, 1);
        ls0 += __shfl_xor_sync(0xffffffffu, ls0, 2);
        ls1 += __shfl_xor_sync(0xffffffffu, ls1, 1);
        ls1 += __shfl_xor_sync(0xffffffffu, ls1, 2);
        l0 = l0 * al0 + ls0;
        l1 = l1 * al1 + ls1;

        // ---- rescale O in regs ----
#pragma unroll
        for (int nt = 0; nt < 8; nt++) {
            o[nt][0] *= al0; o[nt][1] *= al0;
            o[nt][2] *= al1; o[nt][3] *= al1;
        }

        // ---- O += P @ V : shuffle-transpose P n-tile kc into A fragments ----
#pragma unroll
        for (int kc = 0; kc < 8; kc++) {
            float c0 = s[kc][0], c1 = s[kc][1], c2 = s[kc][2], c3 = s[kc][3];
            int src  = (lane & ~3) | (t >> 1);
            float s0 = __shfl_sync(0xffffffffu, c0, src);
            float s1 = __shfl_sync(0xffffffffu, c1, src);
            float s2 = __shfl_sync(0xffffffffu, c2, src);
            float s3 = __shfl_sync(0xffffffffu, c3, src);
            int src2 = src + 2;
            float u0 = __shfl_sync(0xffffffffu, c0, src2);
            float u1 = __shfl_sync(0xffffffffu, c1, src2);
            float u2 = __shfl_sync(0xffffffffu, c2, src2);
            float u3 = __shfl_sync(0xffffffffu, c3, src2);
            bool odd = (t & 1);
            unsigned a0 = tf32u(odd ? s1 : s0);  // row g,   col t
            unsigned a1 = tf32u(odd ? s3 : s2);  // row g+8, col t
            unsigned a2 = tf32u(odd ? u1 : u0);  // row g,   col t+4
            unsigned a3 = tf32u(odd ? u3 : u2);  // row g+8, col t+4
#pragma unroll
            for (int nt = 0; nt < 8; nt++) {
                uint2 b = *(uint2*)&sVT[(nt * 8 + g) * PITCH + 18 * t + 2 * kc];
                mma_tf32(o[nt], a0, a1, a2, a3, b.x, b.y);
            }
        }
        __syncthreads();   // tiles consumed; safe to overwrite next iter
    }

    // ---- epilogue: normalize, store ----
    float inv0 = 1.f / l0, inv1 = 1.f / l1;
#pragma unroll
    for (int nt = 0; nt < 8; nt++) {
        int col = h * DH + nt * 8 + 2 * t;
        float2 w0 = make_float2(o[nt][0] * inv0, o[nt][1] * inv0);
        float2 w1 = make_float2(o[nt][2] * inv1, o[nt][3] * inv1);
        *(float2*)&Og[(size_t)qr0 * D_MODEL + col]       = w0;
        *(float2*)&Og[(size_t)(qr0 + 8) * D_MODEL + col] = w1;
    }
}

// ============================================================
// launcher
// ============================================================
extern "C" void kernel_launch(void* const* d_in, const int* in_sizes, int n_in,
                              void* d_out, int out_size) {
    const float* x      = (const float*)d_in[0];
    const float* coords = (const float*)d_in[1];
    const float* Wq = (const float*)d_in[2]; const float* bq = (const float*)d_in[3];
    const float* Wk = (const float*)d_in[4]; const float* bk = (const float*)d_in[5];
    const float* Wv = (const float*)d_in[6]; const float* bv = (const float*)d_in[7];
    const float* Wo = (const float*)d_in[8]; const float* bo = (const float*)d_in[9];
    float* out = (float*)d_out;

    float *pQ, *pK, *pV, *pAO;
    cudaGetSymbolAddress((void**)&pQ, g_Q);
    cudaGetSymbolAddress((void**)&pK, g_K);
    cudaGetSymbolAddress((void**)&pV, g_V);
    cudaGetSymbolAddress((void**)&pAO, g_AO);

    const size_t FLASH_SMEM = (size_t)(128 * PITCH + 64 * PITCH + 64 * PITCH + 128) * sizeof(float);
    cudaFuncSetAttribute(flash2, cudaFuncAttributeMaxDynamicSharedMemorySize, (int)FLASH_SMEM);

    // QKV projections in one launch
    GemmArgs3 qkv;
    qkv.a[0] = { Wq, bq, pQ };
    qkv.a[1] = { Wk, bk, pK };
    qkv.a[2] = { Wv, bv, pV };
    gemm64<<<dim3(N_TOK / 64, D_MODEL / 64, 3), 128>>>(x, qkv);

    flash2<<<dim3(N_TOK / 128, NH), 256, FLASH_SMEM>>>(pQ, pK, pV, coords, pAO);

    GemmArgs3 og;
    og.a[0] = { Wo, bo, out };
    og.a[1] = og.a[0]; og.a[2] = og.a[0];
    gemm64<<<dim3(N_TOK / 64, D_MODEL / 64, 1), 128>>>(pAO, og);
}

// round 3
// speedup vs baseline: 3.9951x; 1.5226x over previous
#include <cuda_runtime.h>
#include <cuda_bf16.h>

#define N_TOK 4096
#define D_MODEL 512
#define NH 8
#define DH 64
#define PITCH 72    // flash smem row pitch (floats), stride-18 permuted dh
#define GP 40       // gemm smem row pitch (floats), stride-10 permuted k

// ---- device scratch (no cudaMalloc allowed) ----
__device__ float g_Q[(size_t)N_TOK * D_MODEL];
__device__ float g_K[(size_t)N_TOK * D_MODEL];
__device__ float g_V[(size_t)N_TOK * D_MODEL];
__device__ float g_AO[(size_t)N_TOK * D_MODEL];

// ============================================================
// helpers
// ============================================================
__device__ __forceinline__ unsigned tf32u(float x) {
    unsigned u;
    asm("cvt.rna.tf32.f32 %0, %1;" : "=r"(u) : "f"(x));
    return u;
}
__device__ __forceinline__ float tf32f(float x) {
    return __uint_as_float(tf32u(x));
}

// D += A(16x8) @ B(8x8), tf32, m16n8k8 row.col
__device__ __forceinline__ void mma_tf32(float d[4],
    unsigned a0, unsigned a1, unsigned a2, unsigned a3,
    unsigned b0, unsigned b1) {
    asm volatile(
        "mma.sync.aligned.m16n8k8.row.col.f32.tf32.tf32.f32 "
        "{%0,%1,%2,%3},{%4,%5,%6,%7},{%8,%9},{%0,%1,%2,%3};\n"
        : "+f"(d[0]), "+f"(d[1]), "+f"(d[2]), "+f"(d[3])
        : "r"(a0), "r"(a1), "r"(a2), "r"(a3), "r"(b0), "r"(b1));
}

__device__ __forceinline__ float edist(float qx, float qy, float2 k) {
    float dx = qx - k.x, dy = qy - k.y;
    float d2 = dx * dx + dy * dy;
    return d2 > 0.f ? d2 * rsqrtf(d2) : 0.f;
}

// ============================================================
// GEMM v3: C[M,N] = A[M,K] @ W[N,K]^T + bias[N]
// raw mma m16n8k8 tf32, CTA tile 128x128, 256 thr, warp tile 32x64.
// smem: single buffer, k-step 32, stride-10 permuted (conflict-free).
// ============================================================
struct GemmArgs { const float* W; const float* bias; float* C; };
struct GemmArgs3 { GemmArgs a[3]; };

__global__ __launch_bounds__(256, 2) void gemm128(
    const float* __restrict__ A, GemmArgs3 args) {
    const float* __restrict__ W    = args.a[blockIdx.z].W;
    const float* __restrict__ bias = args.a[blockIdx.z].bias;
    float* __restrict__ C          = args.a[blockIdx.z].C;

    __shared__ float sA[128 * GP];
    __shared__ float sW[128 * GP];

    const int m0 = blockIdx.x * 128, n0 = blockIdx.y * 128;
    const int tid = threadIdx.x;
    const int warp = tid >> 5, lane = tid & 31;
    const int g = lane >> 2, t = lane & 3;
    const int wm = warp >> 1, wn = warp & 1;

    const int lr = tid >> 3;              // load row (within 128)
    const int lb = tid & 7;               // load k-group (0..7)
    const int lc4 = lb << 2;              // k-offset within 32

    float4 ra[4], rw[4];
#pragma unroll
    for (int p = 0; p < 4; p++) {
        ra[p] = *(const float4*)&A[(size_t)(m0 + lr + p * 32) * D_MODEL + lc4];
        rw[p] = *(const float4*)&W[(size_t)(n0 + lr + p * 32) * D_MODEL + lc4];
    }

    float acc[2][8][4];
#pragma unroll
    for (int mt = 0; mt < 2; mt++)
#pragma unroll
        for (int nt = 0; nt < 8; nt++)
#pragma unroll
            for (int e = 0; e < 4; e++) acc[mt][nt][e] = 0.f;

    for (int ks = 0; ks < 16; ks++) {
        // store staged regs -> smem (tf32, stride-10 permuted)
#pragma unroll
        for (int p = 0; p < 4; p++) {
            float* rowA = &sA[(lr + p * 32) * GP + lb];
            rowA[0]  = tf32f(ra[p].x); rowA[10] = tf32f(ra[p].y);
            rowA[20] = tf32f(ra[p].z); rowA[30] = tf32f(ra[p].w);
            float* rowW = &sW[(lr + p * 32) * GP + lb];
            rowW[0]  = tf32f(rw[p].x); rowW[10] = tf32f(rw[p].y);
            rowW[20] = tf32f(rw[p].z); rowW[30] = tf32f(rw[p].w);
        }
        __syncthreads();

        if (ks < 15) {
            int kt = (ks + 1) * 32;
#pragma unroll
            for (int p = 0; p < 4; p++) {
                ra[p] = *(const float4*)&A[(size_t)(m0 + lr + p * 32) * D_MODEL + kt + lc4];
                rw[p] = *(const float4*)&W[(size_t)(n0 + lr + p * 32) * D_MODEL + kt + lc4];
            }
        }

#pragma unroll
        for (int kc = 0; kc < 4; kc++) {
            uint2 a[4];
#pragma unroll
            for (int s = 0; s < 4; s++)
                a[s] = *(uint2*)&sA[(wm * 32 + g + 8 * s) * GP + 10 * t + 2 * kc];
#pragma unroll
            for (int nt = 0; nt < 8; nt++) {
                uint2 b = *(uint2*)&sW[(wn * 64 + nt * 8 + g) * GP + 10 * t + 2 * kc];
                mma_tf32(acc[0][nt], a[0].x, a[1].x, a[0].y, a[1].y, b.x, b.y);
                mma_tf32(acc[1][nt], a[2].x, a[3].x, a[2].y, a[3].y, b.x, b.y);
            }
        }
        __syncthreads();
    }

    // epilogue: add bias, direct float2 stores
#pragma unroll
    for (int nt = 0; nt < 8; nt++) {
        int col = n0 + wn * 64 + nt * 8 + 2 * t;
        float2 bb = *(const float2*)&bias[col];
#pragma unroll
        for (int mt = 0; mt < 2; mt++) {
            int r0 = m0 + wm * 32 + mt * 16 + g;
            float2 w0 = make_float2(acc[mt][nt][0] + bb.x, acc[mt][nt][1] + bb.y);
            float2 w1 = make_float2(acc[mt][nt][2] + bb.x, acc[mt][nt][3] + bb.y);
            *(float2*)&C[(size_t)r0 * D_MODEL + col] = w0;
            *(float2*)&C[(size_t)(r0 + 8) * D_MODEL + col] = w1;
        }
    }
}

// ============================================================
// Flash attention v3: register-resident S/O, raw mma tf32,
// on-the-fly distance bias, software-pipelined K/V loads,
// row-major V (conflict-free) with 2xLDS.32 B-fragments.
// CTA: 256 thr (8 warps), q-tile 128 rows, k-tile 64.
// ============================================================
__global__ __launch_bounds__(256, 2) void flash3(
    const float* __restrict__ Qg, const float* __restrict__ Kg,
    const float* __restrict__ Vg, const float* __restrict__ coords,
    float* __restrict__ Og) {
    extern __shared__ float sm[];
    float* sQ  = sm;                     // [128][PITCH] permuted dh
    float* sK  = sQ + 128 * PITCH;       // [64 tok][PITCH] permuted dh
    float* sV  = sK + 64 * PITCH;        // [64 tok][PITCH] permuted dh (row-major)
    float* sKC = sV + 64 * PITCH;        // [64] float2 coords

    const int tid = threadIdx.x;
    const int warp = tid >> 5, lane = tid & 31;
    const int g = lane >> 2, t = lane & 3;
    const int q0 = blockIdx.x * 128;
    const int h  = blockIdx.y;
    const float slope = exp2f(-(float)(h + 1));   // get_slopes(8) = 2^-(h+1)
    const float* __restrict__ coords2f = coords;

    // ---- load Q tile: scaled by 1/8, tf32, permuted ----
    for (int i = tid; i < 128 * 16; i += 256) {
        int r = i >> 4, c4 = (i & 15) << 2;
        float4 v = *(const float4*)&Qg[(size_t)(q0 + r) * D_MODEL + h * DH + c4];
        float* row = &sQ[r * PITCH];
        int b = c4 >> 2;
        row[b]      = tf32f(v.x * 0.125f);
        row[b + 18] = tf32f(v.y * 0.125f);
        row[b + 36] = tf32f(v.z * 0.125f);
        row[b + 54] = tf32f(v.w * 0.125f);
    }
    // per-thread q coords (rows warp*16+g and +8)
    const int qr0 = q0 + warp * 16 + g;
    const float qx0 = coords2f[2 * qr0],       qy0 = coords2f[2 * qr0 + 1];
    const float qx1 = coords2f[2 * (qr0 + 8)], qy1 = coords2f[2 * (qr0 + 8) + 1];

    // PV B-fragment dh offset for this thread (permuted position of dh = nt*8+g)
    const int pvoff = (g & 3) * 18 + (g >> 2);   // + 2*nt at use

    float o[8][4];
#pragma unroll
    for (int nt = 0; nt < 8; nt++) { o[nt][0] = o[nt][1] = o[nt][2] = o[nt][3] = 0.f; }
    float m0 = -1e30f, m1 = -1e30f, l0 = 0.f, l1 = 0.f;

    // ---- prefetch K tile 0 + coords 0 ----
    const int kr = tid >> 4;        // K/V load row (0..15) + p*16? (i = tid + p*256 -> r = i>>4)
    const int kb = tid & 15;        // dh group
    float4 kre[4];
#pragma unroll
    for (int p = 0; p < 4; p++)
        kre[p] = *(const float4*)&Kg[(size_t)(kr + p * 16) * D_MODEL + h * DH + (kb << 2)];
    float2 kc2 = make_float2(0.f, 0.f);
    if (tid < 64) kc2 = *(const float2*)&coords2f[2 * tid];

    for (int k0 = 0; k0 < N_TOK; k0 += 64) {
        __syncthreads();   // (1) all prior-iter reads of sK/sV done

        // store prefetched K tile + coords
#pragma unroll
        for (int p = 0; p < 4; p++) {
            float* row = &sK[(kr + p * 16) * PITCH + kb];
            row[0]  = tf32f(kre[p].x); row[18] = tf32f(kre[p].y);
            row[36] = tf32f(kre[p].z); row[54] = tf32f(kre[p].w);
        }
        if (tid < 64) *(float2*)&sKC[2 * tid] = kc2;
        __syncthreads();   // (2) sK + coords visible

        // issue V half A loads (rows 0..31)
        float4 vA0 = *(const float4*)&Vg[(size_t)(k0 + kr) * D_MODEL + h * DH + (kb << 2)];
        float4 vA1 = *(const float4*)&Vg[(size_t)(k0 + kr + 16) * D_MODEL + h * DH + (kb << 2)];

        // ---- S = Q @ K^T ----
        float s[8][4];
#pragma unroll
        for (int nt = 0; nt < 8; nt++) { s[nt][0] = s[nt][1] = s[nt][2] = s[nt][3] = 0.f; }
#pragma unroll
        for (int kc = 0; kc < 8; kc++) {
            uint2 aA = *(uint2*)&sQ[(warp * 16 + g) * PITCH + 18 * t + 2 * kc];
            uint2 aB = *(uint2*)&sQ[(warp * 16 + g + 8) * PITCH + 18 * t + 2 * kc];
#pragma unroll
            for (int nt = 0; nt < 8; nt++) {
                uint2 b = *(uint2*)&sK[(nt * 8 + g) * PITCH + 18 * t + 2 * kc];
                mma_tf32(s[nt], aA.x, aB.x, aA.y, aB.y, b.x, b.y);
            }
        }

        // store V half A, issue half B loads (rows 32..63)
        {
            float* row = &sV[kr * PITCH + kb];
            row[0] = tf32f(vA0.x); row[18] = tf32f(vA0.y);
            row[36] = tf32f(vA0.z); row[54] = tf32f(vA0.w);
            row = &sV[(kr + 16) * PITCH + kb];
            row[0] = tf32f(vA1.x); row[18] = tf32f(vA1.y);
            row[36] = tf32f(vA1.z); row[54] = tf32f(vA1.w);
        }
        float4 vB0 = *(const float4*)&Vg[(size_t)(k0 + kr + 32) * D_MODEL + h * DH + (kb << 2)];
        float4 vB1 = *(const float4*)&Vg[(size_t)(k0 + kr + 48) * D_MODEL + h * DH + (kb << 2)];

        // prefetch next K tile + coords (latency covered by softmax + PV)
        if (k0 + 64 < N_TOK) {
#pragma unroll
            for (int p = 0; p < 4; p++)
                kre[p] = *(const float4*)&Kg[(size_t)(k0 + 64 + kr + p * 16) * D_MODEL + h * DH + (kb << 2)];
            if (tid < 64) kc2 = *(const float2*)&coords2f[2 * (k0 + 64 + tid)];
        }

        // ---- bias (on-the-fly distance) + row max ----
        float mt0 = -1e30f, mt1 = -1e30f;
#pragma unroll
        for (int nt = 0; nt < 8; nt++) {
            float2 ka = ((float2*)sKC)[nt * 8 + 2 * t];
            float2 kb2 = ((float2*)sKC)[nt * 8 + 2 * t + 1];
            s[nt][0] -= slope * edist(qx0, qy0, ka);
            s[nt][1] -= slope * edist(qx0, qy0, kb2);
            s[nt][2] -= slope * edist(qx1, qy1, ka);
            s[nt][3] -= slope * edist(qx1, qy1, kb2);
            mt0 = fmaxf(mt0, fmaxf(s[nt][0], s[nt][1]));
            mt1 = fmaxf(mt1, fmaxf(s[nt][2], s[nt][3]));
        }
        mt0 = fmaxf(mt0, __shfl_xor_sync(0xffffffffu, mt0, 1));
        mt0 = fmaxf(mt0, __shfl_xor_sync(0xffffffffu, mt0, 2));
        mt1 = fmaxf(mt1, __shfl_xor_sync(0xffffffffu, mt1, 1));
        mt1 = fmaxf(mt1, __shfl_xor_sync(0xffffffffu, mt1, 2));

        float mn0 = fmaxf(m0, mt0), mn1 = fmaxf(m1, mt1);
        float al0 = __expf(m0 - mn0), al1 = __expf(m1 - mn1);
        m0 = mn0; m1 = mn1;

        // ---- P = exp(S - m), row sums ----
        float ls0 = 0.f, ls1 = 0.f;
#pragma unroll
        for (int nt = 0; nt < 8; nt++) {
            s[nt][0] = __expf(s[nt][0] - mn0);
            s[nt][1] = __expf(s[nt][1] - mn0);
            s[nt][2] = __expf(s[nt][2] - mn1);
            s[nt][3] = __expf(s[nt][3] - mn1);
            ls0 += s[nt][0] + s[nt][1];
            ls1 += s[nt][2] + s[nt][3];
        }
        ls0 += __shfl_xor_sync(0xffffffffu, ls0, 1);
        ls0 += __shfl_xor_sync(0xffffffffu, ls0, 2);
        ls1 += __shfl_xor_sync(0xffffffffu, ls1, 1);
        ls1 += __shfl_xor_sync(0xffffffffu, ls1, 2);
        l0 = l0 * al0 + ls0;
        l1 = l1 * al1 + ls1;

        // ---- rescale O in regs ----
#pragma unroll
        for (int nt = 0; nt < 8; nt++) {
            o[nt][0] *= al0; o[nt][1] *= al0;
            o[nt][2] *= al1; o[nt][3] *= al1;
        }

        // store V half B
        {
            float* row = &sV[(kr + 32) * PITCH + kb];
            row[0] = tf32f(vB0.x); row[18] = tf32f(vB0.y);
            row[36] = tf32f(vB0.z); row[54] = tf32f(vB0.w);
            row = &sV[(kr + 48) * PITCH + kb];
            row[0] = tf32f(vB1.x); row[18] = tf32f(vB1.y);
            row[36] = tf32f(vB1.z); row[54] = tf32f(vB1.w);
        }
        __syncthreads();   // (3) sV visible

        // ---- O += P @ V : shuffle-transpose P, B-frags from row-major V ----
#pragma unroll
        for (int kc = 0; kc < 8; kc++) {
            float c0 = s[kc][0], c1 = s[kc][1], c2 = s[kc][2], c3 = s[kc][3];
            int src  = (lane & ~3) | (t >> 1);
            float s0 = __shfl_sync(0xffffffffu, c0, src);
            float s1 = __shfl_sync(0xffffffffu, c1, src);
            float s2 = __shfl_sync(0xffffffffu, c2, src);
            float s3 = __shfl_sync(0xffffffffu, c3, src);
            int src2 = src + 2;
            float u0 = __shfl_sync(0xffffffffu, c0, src2);
            float u1 = __shfl_sync(0xffffffffu, c1, src2);
            float u2 = __shfl_sync(0xffffffffu, c2, src2);
            float u3 = __shfl_sync(0xffffffffu, c3, src2);
            bool odd = (t & 1);
            unsigned a0 = tf32u(odd ? s1 : s0);  // row g,   col t
            unsigned a1 = tf32u(odd ? s3 : s2);  // row g+8, col t
            unsigned a2 = tf32u(odd ? u1 : u0);  // row g,   col t+4
            unsigned a3 = tf32u(odd ? u3 : u2);  // row g+8, col t+4
            const float* rb0 = &sV[(8 * kc + t) * PITCH + pvoff];
            const float* rb1 = rb0 + 4 * PITCH;
#pragma unroll
            for (int nt = 0; nt < 8; nt++) {
                unsigned b0 = __float_as_uint(rb0[2 * nt]);
                unsigned b1 = __float_as_uint(rb1[2 * nt]);
                mma_tf32(o[nt], a0, a1, a2, a3, b0, b1);
            }
        }
    }

    // ---- epilogue: normalize, store ----
    float inv0 = 1.f / l0, inv1 = 1.f / l1;
#pragma unroll
    for (int nt = 0; nt < 8; nt++) {
        int col = h * DH + nt * 8 + 2 * t;
        float2 w0 = make_float2(o[nt][0] * inv0, o[nt][1] * inv0);
        float2 w1 = make_float2(o[nt][2] * inv1, o[nt][3] * inv1);
        *(float2*)&Og[(size_t)qr0 * D_MODEL + col]       = w0;
        *(float2*)&Og[(size_t)(qr0 + 8) * D_MODEL + col] = w1;
    }
}

// ============================================================
// launcher
// ============================================================
extern "C" void kernel_launch(void* const* d_in, const int* in_sizes, int n_in,
                              void* d_out, int out_size) {
    const float* x      = (const float*)d_in[0];
    const float* coords = (const float*)d_in[1];
    const float* Wq = (const float*)d_in[2]; const float* bq = (const float*)d_in[3];
    const float* Wk = (const float*)d_in[4]; const float* bk = (const float*)d_in[5];
    const float* Wv = (const float*)d_in[6]; const float* bv = (const float*)d_in[7];
    const float* Wo = (const float*)d_in[8]; const float* bo = (const float*)d_in[9];
    float* out = (float*)d_out;

    float *pQ, *pK, *pV, *pAO;
    cudaGetSymbolAddress((void**)&pQ, g_Q);
    cudaGetSymbolAddress((void**)&pK, g_K);
    cudaGetSymbolAddress((void**)&pV, g_V);
    cudaGetSymbolAddress((void**)&pAO, g_AO);

    const size_t FLASH_SMEM = (size_t)(128 * PITCH + 64 * PITCH + 64 * PITCH + 128) * sizeof(float);
    cudaFuncSetAttribute(flash3, cudaFuncAttributeMaxDynamicSharedMemorySize, (int)FLASH_SMEM);

    // QKV projections in one launch
    GemmArgs3 qkv;
    qkv.a[0] = { Wq, bq, pQ };
    qkv.a[1] = { Wk, bk, pK };
    qkv.a[2] = { Wv, bv, pV };
    gemm128<<<dim3(N_TOK / 128, D_MODEL / 128, 3), 256>>>(x, qkv);

    flash3<<<dim3(N_TOK / 128, NH), 256, FLASH_SMEM>>>(pQ, pK, pV, coords, pAO);

    GemmArgs3 og;
    og.a[0] = { Wo, bo, out };
    og.a[1] = og.a[0]; og.a[2] = og.a[0];
    gemm128<<<dim3(N_TOK / 128, D_MODEL / 128, 1), 256>>>(pAO, og);
}

// round 4
// speedup vs baseline: 4.5271x; 1.1332x over previous
#include <cuda_runtime.h>
#include <cuda_bf16.h>

#define N_TOK 4096
#define D_MODEL 512
#define NH 8
#define DH 64
#define PITCH 72    // flash smem row pitch (floats), stride-18 permuted dh
#define GP 40       // gemm smem row pitch (floats), stride-10 permuted k

// ---- device scratch (no cudaMalloc allowed) ----
__device__ float g_Q[(size_t)N_TOK * D_MODEL];
__device__ float g_K[(size_t)N_TOK * D_MODEL];
__device__ float g_V[(size_t)N_TOK * D_MODEL];
__device__ float g_AO[(size_t)N_TOK * D_MODEL];

// ============================================================
// helpers
// ============================================================
__device__ __forceinline__ unsigned tf32u(float x) {
    unsigned u;
    asm("cvt.rna.tf32.f32 %0, %1;" : "=r"(u) : "f"(x));
    return u;
}
__device__ __forceinline__ float tf32f(float x) {
    return __uint_as_float(tf32u(x));
}
__device__ __forceinline__ float ex2f(float x) {
    float y;
    asm("ex2.approx.f32 %0, %1;" : "=f"(y) : "f"(x));
    return y;
}
__device__ __forceinline__ float sqrt_ap(float x) {
    float y;
    asm("sqrt.approx.f32 %0, %1;" : "=f"(y) : "f"(x));
    return y;
}

// D += A(16x8) @ B(8x8), tf32, m16n8k8 row.col
__device__ __forceinline__ void mma_tf32(float d[4],
    unsigned a0, unsigned a1, unsigned a2, unsigned a3,
    unsigned b0, unsigned b1) {
    asm volatile(
        "mma.sync.aligned.m16n8k8.row.col.f32.tf32.tf32.f32 "
        "{%0,%1,%2,%3},{%4,%5,%6,%7},{%8,%9},{%0,%1,%2,%3};\n"
        : "+f"(d[0]), "+f"(d[1]), "+f"(d[2]), "+f"(d[3])
        : "r"(a0), "r"(a1), "r"(a2), "r"(a3), "r"(b0), "r"(b1));
}

// distance (5 ops, no select; sqrt.approx(0) == 0)
__device__ __forceinline__ float edist(float qx, float qy, float2 k) {
    float dx = qx - k.x, dy = qy - k.y;
    return sqrt_ap(__fmaf_rn(dy, dy, dx * dx));
}

// ============================================================
// GEMM: C[M,N] = A[M,K] @ W[N,K]^T + bias[N]
// raw mma m16n8k8 tf32, CTA tile 128x128, 256 thr, warp tile 32x64.
// ============================================================
struct GemmArgs { const float* W; const float* bias; float* C; };
struct GemmArgs3 { GemmArgs a[3]; };

__global__ __launch_bounds__(256, 2) void gemm128(
    const float* __restrict__ A, GemmArgs3 args) {
    const float* __restrict__ W    = args.a[blockIdx.z].W;
    const float* __restrict__ bias = args.a[blockIdx.z].bias;
    float* __restrict__ C          = args.a[blockIdx.z].C;

    __shared__ float sA[128 * GP];
    __shared__ float sW[128 * GP];

    const int m0 = blockIdx.x * 128, n0 = blockIdx.y * 128;
    const int tid = threadIdx.x;
    const int warp = tid >> 5, lane = tid & 31;
    const int g = lane >> 2, t = lane & 3;
    const int wm = warp >> 1, wn = warp & 1;

    const int lr = tid >> 3;
    const int lb = tid & 7;
    const int lc4 = lb << 2;

    float4 ra[4], rw[4];
#pragma unroll
    for (int p = 0; p < 4; p++) {
        ra[p] = *(const float4*)&A[(size_t)(m0 + lr + p * 32) * D_MODEL + lc4];
        rw[p] = *(const float4*)&W[(size_t)(n0 + lr + p * 32) * D_MODEL + lc4];
    }

    float acc[2][8][4];
#pragma unroll
    for (int mt = 0; mt < 2; mt++)
#pragma unroll
        for (int nt = 0; nt < 8; nt++)
#pragma unroll
            for (int e = 0; e < 4; e++) acc[mt][nt][e] = 0.f;

    for (int ks = 0; ks < 16; ks++) {
#pragma unroll
        for (int p = 0; p < 4; p++) {
            float* rowA = &sA[(lr + p * 32) * GP + lb];
            rowA[0]  = tf32f(ra[p].x); rowA[10] = tf32f(ra[p].y);
            rowA[20] = tf32f(ra[p].z); rowA[30] = tf32f(ra[p].w);
            float* rowW = &sW[(lr + p * 32) * GP + lb];
            rowW[0]  = tf32f(rw[p].x); rowW[10] = tf32f(rw[p].y);
            rowW[20] = tf32f(rw[p].z); rowW[30] = tf32f(rw[p].w);
        }
        __syncthreads();

        if (ks < 15) {
            int kt = (ks + 1) * 32;
#pragma unroll
            for (int p = 0; p < 4; p++) {
                ra[p] = *(const float4*)&A[(size_t)(m0 + lr + p * 32) * D_MODEL + kt + lc4];
                rw[p] = *(const float4*)&W[(size_t)(n0 + lr + p * 32) * D_MODEL + kt + lc4];
            }
        }

#pragma unroll
        for (int kc = 0; kc < 4; kc++) {
            uint2 a[4];
#pragma unroll
            for (int s = 0; s < 4; s++)
                a[s] = *(uint2*)&sA[(wm * 32 + g + 8 * s) * GP + 10 * t + 2 * kc];
#pragma unroll
            for (int nt = 0; nt < 8; nt++) {
                uint2 b = *(uint2*)&sW[(wn * 64 + nt * 8 + g) * GP + 10 * t + 2 * kc];
                mma_tf32(acc[0][nt], a[0].x, a[1].x, a[0].y, a[1].y, b.x, b.y);
                mma_tf32(acc[1][nt], a[2].x, a[3].x, a[2].y, a[3].y, b.x, b.y);
            }
        }
        __syncthreads();
    }

#pragma unroll
    for (int nt = 0; nt < 8; nt++) {
        int col = n0 + wn * 64 + nt * 8 + 2 * t;
        float2 bb = *(const float2*)&bias[col];
#pragma unroll
        for (int mt = 0; mt < 2; mt++) {
            int r0 = m0 + wm * 32 + mt * 16 + g;
            float2 w0 = make_float2(acc[mt][nt][0] + bb.x, acc[mt][nt][1] + bb.y);
            float2 w1 = make_float2(acc[mt][nt][2] + bb.x, acc[mt][nt][3] + bb.y);
            *(float2*)&C[(size_t)r0 * D_MODEL + col] = w0;
            *(float2*)&C[(size_t)(r0 + 8) * D_MODEL + col] = w1;
        }
    }
}

// ============================================================
// Flash attention v4: register-resident S/O, raw mma tf32.
// KEY TRICK: V rows stored with token permutation sigma(j) = (j>>1)|((j&1)<<2)
// within each 8-token group, so the S accumulator registers ARE the PV
// A-fragments (a0,a1,a2,a3 = s[0],s[2],s[1],s[3]) — no shuffles, no sels.
// Softmax in exp2 domain (log2e folded into Q scale and slope).
// CTA: 256 thr (8 warps), q-tile 128 rows, k-tile 64, 3 syncs/iter.
// ============================================================
__global__ __launch_bounds__(256, 2) void flash4(
    const float* __restrict__ Qg, const float* __restrict__ Kg,
    const float* __restrict__ Vg, const float* __restrict__ coords,
    float* __restrict__ Og) {
    extern __shared__ float sm[];
    float* sQ  = sm;                     // [128][PITCH] permuted dh
    float* sK  = sQ + 128 * PITCH;       // [64 tok][PITCH] permuted dh
    float* sV  = sK + 64 * PITCH;        // [64 tok, sigma-permuted][PITCH] permuted dh
    float* sKC = sV + 64 * PITCH;        // [64] float2 coords

    const int tid = threadIdx.x;
    const int warp = tid >> 5, lane = tid & 31;
    const int g = lane >> 2, t = lane & 3;
    const int q0 = blockIdx.x * 128;
    const int h  = blockIdx.y;
    const float LOG2E = 1.44269504f;
    const float slope2 = exp2f(-(float)(h + 1)) * LOG2E;  // slope * log2(e)
    const float qscale = 0.125f * LOG2E;                  // 1/sqrt(dh) * log2(e)
    const float* __restrict__ coords2f = coords;

    // ---- load Q tile: scaled, tf32, permuted dh ----
    for (int i = tid; i < 128 * 16; i += 256) {
        int r = i >> 4, c4 = (i & 15) << 2;
        float4 v = *(const float4*)&Qg[(size_t)(q0 + r) * D_MODEL + h * DH + c4];
        float* row = &sQ[r * PITCH];
        int b = c4 >> 2;
        row[b]      = tf32f(v.x * qscale);
        row[b + 18] = tf32f(v.y * qscale);
        row[b + 36] = tf32f(v.z * qscale);
        row[b + 54] = tf32f(v.w * qscale);
    }
    const int qr0 = q0 + warp * 16 + g;
    const float qx0 = coords2f[2 * qr0],       qy0 = coords2f[2 * qr0 + 1];
    const float qx1 = coords2f[2 * (qr0 + 8)], qy1 = coords2f[2 * (qr0 + 8) + 1];

    // PV B-fragment dh offset (permuted position of dh = nt*8+g; +2*nt at use)
    const int pvoff = (g & 3) * 18 + (g >> 2);

    float o[8][4];
#pragma unroll
    for (int nt = 0; nt < 8; nt++) { o[nt][0] = o[nt][1] = o[nt][2] = o[nt][3] = 0.f; }
    float m0 = -1e30f, m1 = -1e30f, l0 = 0.f, l1 = 0.f;

    // ---- K/V loader lane mapping + sigma-permuted V row ----
    const int kr = tid >> 4;            // 0..15
    const int kb = tid & 15;            // dh group
    const int krlo = kr & 7;
    const int pkr = (kr & 8) | ((krlo >> 1) | ((krlo & 1) << 2));  // sigma within 8-group

    // ---- prefetch K tile 0 + coords 0 ----
    float4 kre[4];
#pragma unroll
    for (int p = 0; p < 4; p++)
        kre[p] = *(const float4*)&Kg[(size_t)(kr + p * 16) * D_MODEL + h * DH + (kb << 2)];
    float2 kc2 = make_float2(0.f, 0.f);
    if (tid < 64) kc2 = *(const float2*)&coords2f[2 * tid];

    for (int k0 = 0; k0 < N_TOK; k0 += 64) {
        __syncthreads();   // (1) prior-iter reads of sK/sV done

        // store prefetched K tile + coords
#pragma unroll
        for (int p = 0; p < 4; p++) {
            float* row = &sK[(kr + p * 16) * PITCH + kb];
            row[0]  = tf32f(kre[p].x); row[18] = tf32f(kre[p].y);
            row[36] = tf32f(kre[p].z); row[54] = tf32f(kre[p].w);
        }
        if (tid < 64) *(float2*)&sKC[2 * tid] = kc2;
        __syncthreads();   // (2) sK + coords visible

        // issue V half A loads (rows 0..31)
        float4 vA0 = *(const float4*)&Vg[(size_t)(k0 + kr) * D_MODEL + h * DH + (kb << 2)];
        float4 vA1 = *(const float4*)&Vg[(size_t)(k0 + kr + 16) * D_MODEL + h * DH + (kb << 2)];

        // ---- S = Q @ K^T ----
        float s[8][4];
#pragma unroll
        for (int nt = 0; nt < 8; nt++) { s[nt][0] = s[nt][1] = s[nt][2] = s[nt][3] = 0.f; }
#pragma unroll
        for (int kc = 0; kc < 8; kc++) {
            uint2 aA = *(uint2*)&sQ[(warp * 16 + g) * PITCH + 18 * t + 2 * kc];
            uint2 aB = *(uint2*)&sQ[(warp * 16 + g + 8) * PITCH + 18 * t + 2 * kc];
#pragma unroll
            for (int nt = 0; nt < 8; nt++) {
                uint2 b = *(uint2*)&sK[(nt * 8 + g) * PITCH + 18 * t + 2 * kc];
                mma_tf32(s[nt], aA.x, aB.x, aA.y, aB.y, b.x, b.y);
            }
        }

        // store V half A (sigma-permuted rows), issue half B loads
        {
            float* row = &sV[pkr * PITCH + kb];
            row[0] = tf32f(vA0.x); row[18] = tf32f(vA0.y);
            row[36] = tf32f(vA0.z); row[54] = tf32f(vA0.w);
            row = &sV[(pkr + 16) * PITCH + kb];
            row[0] = tf32f(vA1.x); row[18] = tf32f(vA1.y);
            row[36] = tf32f(vA1.z); row[54] = tf32f(vA1.w);
        }
        float4 vB0 = *(const float4*)&Vg[(size_t)(k0 + kr + 32) * D_MODEL + h * DH + (kb << 2)];
        float4 vB1 = *(const float4*)&Vg[(size_t)(k0 + kr + 48) * D_MODEL + h * DH + (kb << 2)];

        // prefetch next K tile + coords
        if (k0 + 64 < N_TOK) {
#pragma unroll
            for (int p = 0; p < 4; p++)
                kre[p] = *(const float4*)&Kg[(size_t)(k0 + 64 + kr + p * 16) * D_MODEL + h * DH + (kb << 2)];
            if (tid < 64) kc2 = *(const float2*)&coords2f[2 * (k0 + 64 + tid)];
        }

        // ---- bias (on-the-fly distance, log2 domain) + row max ----
        float mt0 = -1e30f, mt1 = -1e30f;
#pragma unroll
        for (int nt = 0; nt < 8; nt++) {
            float2 ka  = ((float2*)sKC)[nt * 8 + 2 * t];
            float2 kb2 = ((float2*)sKC)[nt * 8 + 2 * t + 1];
            float da = edist(qx0, qy0, ka), db = edist(qx0, qy0, kb2);
            float dc = edist(qx1, qy1, ka), dd = edist(qx1, qy1, kb2);
            s[nt][0] = __fmaf_rn(-slope2, da, s[nt][0]);
            s[nt][1] = __fmaf_rn(-slope2, db, s[nt][1]);
            s[nt][2] = __fmaf_rn(-slope2, dc, s[nt][2]);
            s[nt][3] = __fmaf_rn(-slope2, dd, s[nt][3]);
            mt0 = fmaxf(mt0, fmaxf(s[nt][0], s[nt][1]));
            mt1 = fmaxf(mt1, fmaxf(s[nt][2], s[nt][3]));
        }
        mt0 = fmaxf(mt0, __shfl_xor_sync(0xffffffffu, mt0, 1));
        mt0 = fmaxf(mt0, __shfl_xor_sync(0xffffffffu, mt0, 2));
        mt1 = fmaxf(mt1, __shfl_xor_sync(0xffffffffu, mt1, 1));
        mt1 = fmaxf(mt1, __shfl_xor_sync(0xffffffffu, mt1, 2));

        float mn0 = fmaxf(m0, mt0), mn1 = fmaxf(m1, mt1);
        float al0 = ex2f(m0 - mn0), al1 = ex2f(m1 - mn1);
        m0 = mn0; m1 = mn1;

        // ---- P = exp2(S - m), row sums ----
        float ls0 = 0.f, ls1 = 0.f;
#pragma unroll
        for (int nt = 0; nt < 8; nt++) {
            s[nt][0] = ex2f(s[nt][0] - mn0);
            s[nt][1] = ex2f(s[nt][1] - mn0);
            s[nt][2] = ex2f(s[nt][2] - mn1);
            s[nt][3] = ex2f(s[nt][3] - mn1);
            ls0 += s[nt][0] + s[nt][1];
            ls1 += s[nt][2] + s[nt][3];
        }
        ls0 += __shfl_xor_sync(0xffffffffu, ls0, 1);
        ls0 += __shfl_xor_sync(0xffffffffu, ls0, 2);
        ls1 += __shfl_xor_sync(0xffffffffu, ls1, 1);
        ls1 += __shfl_xor_sync(0xffffffffu, ls1, 2);
        l0 = l0 * al0 + ls0;
        l1 = l1 * al1 + ls1;

        // ---- rescale O ----
#pragma unroll
        for (int nt = 0; nt < 8; nt++) {
            o[nt][0] *= al0; o[nt][1] *= al0;
            o[nt][2] *= al1; o[nt][3] *= al1;
        }

        // store V half B (sigma-permuted rows)
        {
            float* row = &sV[(pkr + 32) * PITCH + kb];
            row[0] = tf32f(vB0.x); row[18] = tf32f(vB0.y);
            row[36] = tf32f(vB0.z); row[54] = tf32f(vB0.w);
            row = &sV[(pkr + 48) * PITCH + kb];
            row[0] = tf32f(vB1.x); row[18] = tf32f(vB1.y);
            row[36] = tf32f(vB1.z); row[54] = tf32f(vB1.w);
        }
        __syncthreads();   // (3) sV visible

        // ---- O += P @ V : accumulator regs ARE the A-fragments ----
#pragma unroll
        for (int kc = 0; kc < 8; kc++) {
            unsigned a0 = tf32u(s[kc][0]);   // row g,   A-col t   (token 8kc+2t)
            unsigned a1 = tf32u(s[kc][2]);   // row g+8, A-col t
            unsigned a2 = tf32u(s[kc][1]);   // row g,   A-col t+4 (token 8kc+2t+1)
            unsigned a3 = tf32u(s[kc][3]);   // row g+8, A-col t+4
            const float* rb0 = &sV[(8 * kc + t) * PITCH + pvoff];
            const float* rb1 = rb0 + 4 * PITCH;
#pragma unroll
            for (int nt = 0; nt < 8; nt++) {
                unsigned b0 = __float_as_uint(rb0[2 * nt]);
                unsigned b1 = __float_as_uint(rb1[2 * nt]);
                mma_tf32(o[nt], a0, a1, a2, a3, b0, b1);
            }
        }
    }

    // ---- epilogue: normalize, store ----
    float inv0 = 1.f / l0, inv1 = 1.f / l1;
#pragma unroll
    for (int nt = 0; nt < 8; nt++) {
        int col = h * DH + nt * 8 + 2 * t;
        float2 w0 = make_float2(o[nt][0] * inv0, o[nt][1] * inv0);
        float2 w1 = make_float2(o[nt][2] * inv1, o[nt][3] * inv1);
        *(float2*)&Og[(size_t)qr0 * D_MODEL + col]       = w0;
        *(float2*)&Og[(size_t)(qr0 + 8) * D_MODEL + col] = w1;
    }
}

// ============================================================
// launcher
// ============================================================
extern "C" void kernel_launch(void* const* d_in, const int* in_sizes, int n_in,
                              void* d_out, int out_size) {
    const float* x      = (const float*)d_in[0];
    const float* coords = (const float*)d_in[1];
    const float* Wq = (const float*)d_in[2]; const float* bq = (const float*)d_in[3];
    const float* Wk = (const float*)d_in[4]; const float* bk = (const float*)d_in[5];
    const float* Wv = (const float*)d_in[6]; const float* bv = (const float*)d_in[7];
    const float* Wo = (const float*)d_in[8]; const float* bo = (const float*)d_in[9];
    float* out = (float*)d_out;

    float *pQ, *pK, *pV, *pAO;
    cudaGetSymbolAddress((void**)&pQ, g_Q);
    cudaGetSymbolAddress((void**)&pK, g_K);
    cudaGetSymbolAddress((void**)&pV, g_V);
    cudaGetSymbolAddress((void**)&pAO, g_AO);

    const size_t FLASH_SMEM = (size_t)(128 * PITCH + 64 * PITCH + 64 * PITCH + 128) * sizeof(float);
    cudaFuncSetAttribute(flash4, cudaFuncAttributeMaxDynamicSharedMemorySize, (int)FLASH_SMEM);

    GemmArgs3 qkv;
    qkv.a[0] = { Wq, bq, pQ };
    qkv.a[1] = { Wk, bk, pK };
    qkv.a[2] = { Wv, bv, pV };
    gemm128<<<dim3(N_TOK / 128, D_MODEL / 128, 3), 256>>>(x, qkv);

    flash4<<<dim3(N_TOK / 128, NH), 256, FLASH_SMEM>>>(pQ, pK, pV, coords, pAO);

    GemmArgs3 og;
    og.a[0] = { Wo, bo, out };
    og.a[1] = og.a[0]; og.a[2] = og.a[0];
    gemm128<<<dim3(N_TOK / 128, D_MODEL / 128, 1), 256>>>(pAO, og);
}